// round 11
// baseline (speedup 1.0000x reference)
#include <cuda_runtime.h>
#include <cuda_bf16.h>
#include <cstdint>

typedef unsigned int u32t;

#define BNUM 1024
#define QNUM 96
#define CNUM 16
#define HNUM 100
#define NSTEPS_K 100
#define QP1 97
#define ROWS (BNUM*CNUM)
#define MT 112
#define GRID 147
#define NTHREADS 448          // 14 warps: pair p=w%7 (16-row slab), sub=w/7 (n-tiles)

#define NP 104            // padded N and K
#define SWB 208           // row stride bytes (104 bf16) = 52 words, conflict-free
#define NTW 7             // n8 tiles per warp (nt = sub*6 + n; tile 6 duplicated)
#define ROW8 (8*SWB)      // 1664

// SMEM byte layout
#define OFF_AHI 0
#define OFF_ALO (128*SWB)            // 26624
#define OFF_W   (2*128*SWB)          // 53248
#define WBUF    (104*SWB)            // 21632  (W1hi W1lo W2hi W2lo W3hi W3lo)
#define OFF_BIAS (OFF_W + 6*WBUF)    // 183040 ; bias[l][104] fp32
#define SMEM_TOTAL (OFF_BIAS + 3*104*4 + 64)   // 184352

extern __shared__ char smbase[];

__device__ __forceinline__ u32t smem_u32(const void* p) {
    u32t a;
    asm("{ .reg .u64 t; cvta.to.shared.u64 t, %1; cvt.u32.u64 %0, t; }" : "=r"(a) : "l"(p));
    return a;
}
__device__ __forceinline__ float tanh_fast(float x) {
    asm("tanh.approx.f32 %0, %0;" : "+f"(x));
    return x;
}
__device__ __forceinline__ u32t ldsw(u32t a) {
    u32t v; asm("ld.shared.b32 %0, [%1];" : "=r"(v) : "r"(a)); return v;
}
__device__ __forceinline__ float ldsf(u32t a) {
    float v; asm("ld.shared.f32 %0, [%1];" : "=f"(v) : "r"(a)); return v;
}
__device__ __forceinline__ void stsw(u32t a, u32t v) {
    asm volatile("st.shared.b32 [%0], %1;" :: "r"(a), "r"(v));
}
__device__ __forceinline__ void split2(float v0, float v1, u32t& hi, u32t& lo) {
    asm("cvt.rn.bf16x2.f32 %0, %1, %2;" : "=r"(hi) : "f"(v1), "f"(v0));
    float h0 = __uint_as_float(hi << 16);
    float h1 = __uint_as_float(hi & 0xFFFF0000u);
    float l0 = v0 - h0, l1 = v1 - h1;
    asm("cvt.rn.bf16x2.f32 %0, %1, %2;" : "=r"(lo) : "f"(l1), "f"(l0));
}
__device__ __forceinline__ void mma16(float (&d)[4], u32t a0, u32t a1, u32t a2, u32t a3,
                                      u32t b0, u32t b1) {
    asm volatile("mma.sync.aligned.m16n8k16.row.col.f32.bf16.bf16.f32 "
        "{%0,%1,%2,%3}, {%4,%5,%6,%7}, {%8,%9}, {%0,%1,%2,%3};"
        : "+f"(d[0]), "+f"(d[1]), "+f"(d[2]), "+f"(d[3])
        : "r"(a0), "r"(a1), "r"(a2), "r"(a3), "r"(b0), "r"(b1));
}
__device__ __forceinline__ void mma8(float (&d)[4], u32t a0, u32t a1, u32t b0) {
    asm volatile("mma.sync.aligned.m16n8k8.row.col.f32.bf16.bf16.f32 "
        "{%0,%1,%2,%3}, {%4,%5}, {%6}, {%0,%1,%2,%3};"
        : "+f"(d[0]), "+f"(d[1]), "+f"(d[2]), "+f"(d[3])
        : "r"(a0), "r"(a1), "r"(b0));
}

__global__ __launch_bounds__(NTHREADS, 1)
void arima_mma_kernel(const float* __restrict__ series,
                      const float* __restrict__ rand_error,
                      const float* __restrict__ W1, const float* __restrict__ b1,
                      const float* __restrict__ W2, const float* __restrict__ b2,
                      const float* __restrict__ W3, const float* __restrict__ b3,
                      float* __restrict__ out)
{
    const u32t sb = smem_u32(smbase);
    const int tid  = threadIdx.x;
    const int w    = tid >> 5;
    const int lane = tid & 31;
    const int l4   = lane & 3;
    const int lr   = lane >> 2;
    const int p    = (w >= 7) ? w - 7 : w;   // row-slab pair id
    const int sub  = (w >= 7) ? 1 : 0;       // n-tile half
    const int ntb  = sub * 6;                // tile base (0 or 6; tile 6 shared)
    const int base = blockIdx.x * MT;
    const int r0   = p * 16 + lr;            // fragment row (0..111)
    const float dt = 1.0f / (float)NSTEPS_K;

    // pair barrier: both warps of pair p (64 threads)
    #define PBAR() asm volatile("bar.sync %0, %1;" :: "r"(p + 1), "r"(64) : "memory")

    // ---- zero smem ----
    for (int i = tid; i < SMEM_TOTAL / 4; i += NTHREADS)
        ((u32t*)smbase)[i] = 0u;
    __syncthreads();

    // ---- weights -> SMEM bf16 hi/lo, row-major [j][k], stride 104 ----
    char* Wp = smbase + OFF_W;
    for (int idx = tid; idx < HNUM * (QNUM + 2); idx += NTHREADS) {
        int j = idx / (QNUM + 2), k = idx - j * (QNUM + 2);
        float v = W1[idx];
        __nv_bfloat16 h = __float2bfloat16(v);
        __nv_bfloat16 l = __float2bfloat16(v - __bfloat162float(h));
        u32t o = (u32t)(j * SWB + k * 2);
        *(__nv_bfloat16*)(Wp + 0 * WBUF + o) = h;
        *(__nv_bfloat16*)(Wp + 1 * WBUF + o) = l;
    }
    for (int idx = tid; idx < HNUM * HNUM; idx += NTHREADS) {
        int j = idx / HNUM, k = idx - j * HNUM;
        float v = W2[idx];
        __nv_bfloat16 h = __float2bfloat16(v);
        __nv_bfloat16 l = __float2bfloat16(v - __bfloat162float(h));
        u32t o = (u32t)(j * SWB + k * 2);
        *(__nv_bfloat16*)(Wp + 2 * WBUF + o) = h;
        *(__nv_bfloat16*)(Wp + 3 * WBUF + o) = l;
    }
    for (int idx = tid; idx < QP1 * HNUM; idx += NTHREADS) {
        int j = idx / HNUM, k = idx - j * HNUM;
        float v = W3[idx];
        __nv_bfloat16 h = __float2bfloat16(v);
        __nv_bfloat16 l = __float2bfloat16(v - __bfloat162float(h));
        u32t o = (u32t)(j * SWB + k * 2);
        *(__nv_bfloat16*)(Wp + 4 * WBUF + o) = h;
        *(__nv_bfloat16*)(Wp + 5 * WBUF + o) = l;
    }
    float* biasp = (float*)(smbase + OFF_BIAS);
    for (int j = tid; j < HNUM; j += NTHREADS) {
        biasp[j]       = b1[j];
        biasp[104 + j] = b2[j];
    }
    for (int j = tid; j < QP1; j += NTHREADS) biasp[208 + j] = b3[j];

    // ---- per-thread global row helpers ----
    const int grow0 = base + r0, grow1 = grow0 + 8;
    const bool gv0 = grow0 < ROWS, gv1 = grow1 < ROWS;
    const int gb0 = grow0 >> 4, gc0 = grow0 & 15;
    const int gb1 = grow1 >> 4, gc1 = grow1 & 15;
    const float* ps0 = series + (size_t)gb0 * (QNUM * CNUM) + gc0;
    const float* ps1 = series + (size_t)gb1 * (QNUM * CNUM) + gc1;
    const float* pr0 = rand_error + (size_t)gb0 * CNUM + gc0;
    const float* pr1 = rand_error + (size_t)gb1 * CNUM + gc1;

    // ---- x0 into D-fragment registers (this warp's 7 tiles) ----
    float x[NTW][4];
    #pragma unroll
    for (int n = 0; n < NTW; n++) {
        int q0 = (ntb + n) * 8 + l4 * 2, q1 = q0 + 1;
        x[n][0] = (gv0 && q0 < QNUM) ? __ldg(ps0 + q0 * CNUM) : (gv0 && q0 == QNUM) ? __ldg(pr0) : 0.0f;
        x[n][1] = (gv0 && q1 < QNUM) ? __ldg(ps0 + q1 * CNUM) : (gv0 && q1 == QNUM) ? __ldg(pr0) : 0.0f;
        x[n][2] = (gv1 && q0 < QNUM) ? __ldg(ps1 + q0 * CNUM) : (gv1 && q0 == QNUM) ? __ldg(pr1) : 0.0f;
        x[n][3] = (gv1 && q1 < QNUM) ? __ldg(ps1 + q1 * CNUM) : (gv1 && q1 == QNUM) ? __ldg(pr1) : 0.0f;
    }

    // store x -> A (bf16 hi/lo); t injected at col 97 (tile 12 = sub1,n6, l4==0)
    const u32t abw = (u32t)(r0 * SWB + l4 * 4);
    const bool tinj = (sub == 1) && (l4 == 0);
    auto store_xA = [&](float tn) {
        #pragma unroll
        for (int n = 0; n < NTW; n++) {
            float v0 = x[n][0], v1 = x[n][1], v2 = x[n][2], v3 = x[n][3];
            if (n == 6 && tinj) { v1 = tn; v3 = tn; }
            u32t bo = abw + (u32t)((ntb + n) * 16);
            u32t hw, lw;
            split2(v0, v1, hw, lw);
            stsw(sb + OFF_AHI + bo, hw);
            stsw(sb + OFF_ALO + bo, lw);
            split2(v2, v3, hw, lw);
            stsw(sb + OFF_AHI + bo + ROW8, hw);
            stsw(sb + OFF_ALO + bo + ROW8, lw);
        }
    };
    store_xA(0.0f);
    __syncthreads();  // weights + all initial A slabs visible

    const u32t aHb = sb + OFF_AHI + (u32t)(r0 * SWB + l4 * 4);
    const u32t aLb = aHb + (u32t)(OFF_ALO - OFF_AHI);
    const u32t wJ  = (u32t)(lr * SWB + l4 * 4);

    for (int s = 0; s < NSTEPS_K; s++) {
        #pragma unroll 1
        for (int l = 0; l < 3; l++) {
            float acc[NTW][4];
            #pragma unroll
            for (int n = 0; n < NTW; n++)
                #pragma unroll
                for (int e = 0; e < 4; e++) acc[n][e] = 0.0f;

            const u32t wHb = sb + OFF_W + (u32t)l * (2 * WBUF) + wJ + (u32t)(ntb * ROW8);
            const u32t wLb = wHb + WBUF;

            #pragma unroll 1
            for (int kc = 0; kc < 6; kc++) {
                u32t ko = (u32t)(kc * 32);
                u32t h0 = ldsw(aHb + ko), h1 = ldsw(aHb + ko + ROW8);
                u32t h2 = ldsw(aHb + ko + 16), h3 = ldsw(aHb + ko + ROW8 + 16);
                u32t g0 = ldsw(aLb + ko), g1 = ldsw(aLb + ko + ROW8);
                u32t g2 = ldsw(aLb + ko + 16), g3 = ldsw(aLb + ko + ROW8 + 16);
                #pragma unroll
                for (int n = 0; n < NTW; n++) {
                    u32t wo = ko + (u32t)(n * ROW8);
                    u32t bh0 = ldsw(wHb + wo), bh1 = ldsw(wHb + wo + 16);
                    u32t bl0 = ldsw(wLb + wo), bl1 = ldsw(wLb + wo + 16);
                    mma16(acc[n], h0, h1, h2, h3, bh0, bh1);
                    mma16(acc[n], h0, h1, h2, h3, bl0, bl1);
                    mma16(acc[n], g0, g1, g2, g3, bh0, bh1);
                }
            }
            {   // k8 tail: k = 96..103
                u32t ko = 192;
                u32t h0 = ldsw(aHb + ko), h1 = ldsw(aHb + ko + ROW8);
                u32t g0 = ldsw(aLb + ko), g1 = ldsw(aLb + ko + ROW8);
                #pragma unroll
                for (int n = 0; n < NTW; n++) {
                    u32t wo = ko + (u32t)(n * ROW8);
                    u32t bh0 = ldsw(wHb + wo);
                    u32t bl0 = ldsw(wLb + wo);
                    mma8(acc[n], h0, h1, bh0);
                    mma8(acc[n], h0, h1, bl0);
                    mma8(acc[n], g0, g1, bh0);
                }
            }
            PBAR();  // pair done reading A before epilogue overwrites

            if (l < 2) {
                // ===== hidden epilogue: A <- tanh(acc + bias) =====
                const u32t bp = sb + OFF_BIAS + (u32t)(l * 416 + ntb * 32 + l4 * 8);
                #pragma unroll
                for (int n = 0; n < NTW; n++) {
                    float bb0 = ldsf(bp + (u32t)(n * 32));
                    float bb1 = ldsf(bp + (u32t)(n * 32) + 4);
                    float v0 = tanh_fast(acc[n][0] + bb0);
                    float v1 = tanh_fast(acc[n][1] + bb1);
                    float v2 = tanh_fast(acc[n][2] + bb0);
                    float v3 = tanh_fast(acc[n][3] + bb1);
                    u32t bo = abw + (u32t)((ntb + n) * 16);
                    u32t hw, lw;
                    split2(v0, v1, hw, lw);
                    stsw(sb + OFF_AHI + bo, hw);
                    stsw(sb + OFF_ALO + bo, lw);
                    split2(v2, v3, hw, lw);
                    stsw(sb + OFF_AHI + bo + ROW8, hw);
                    stsw(sb + OFF_ALO + bo + ROW8, lw);
                }
            } else {
                // ===== Euler epilogue: x += (acc + b3 - noise)*dt; A <- x, t_next =====
                const u32t bp3 = sb + OFF_BIAS + (u32t)(2 * 416 + ntb * 32 + l4 * 8);
                #pragma unroll
                for (int n = 0; n < NTW; n++) {
                    int nt = ntb + n;
                    float bb0 = ldsf(bp3 + (u32t)(n * 32));
                    float bb1 = ldsf(bp3 + (u32t)(n * 32) + 4);
                    float nz0, nz1, nz2, nz3;
                    if (nt < 12) {
                        int q0 = nt * 8 + l4 * 2, q1 = q0 + 1;   // < 96
                        nz0 = gv0 ? __ldg(ps0 + q0 * CNUM) : 0.0f;
                        nz1 = gv0 ? __ldg(ps0 + q1 * CNUM) : 0.0f;
                        nz2 = gv1 ? __ldg(ps1 + q0 * CNUM) : 0.0f;
                        nz3 = gv1 ? __ldg(ps1 + q1 * CNUM) : 0.0f;
                    } else {
                        nz0 = (l4 == 0 && gv0) ? __ldg(pr0) : 0.0f;  // col 96
                        nz1 = 0.0f;
                        nz2 = (l4 == 0 && gv1) ? __ldg(pr1) : 0.0f;
                        nz3 = 0.0f;
                    }
                    x[n][0] = fmaf((acc[n][0] + bb0) - nz0, dt, x[n][0]);
                    x[n][1] = fmaf((acc[n][1] + bb1) - nz1, dt, x[n][1]);
                    x[n][2] = fmaf((acc[n][2] + bb0) - nz2, dt, x[n][2]);
                    x[n][3] = fmaf((acc[n][3] + bb1) - nz3, dt, x[n][3]);
                }
                store_xA((float)(s + 1) * dt);
            }
            PBAR();  // epilogue stores visible to pair's next MMA
        }
    }

    // ---- write result (B, 97, C) from x registers ----
    #pragma unroll
    for (int n = 0; n < NTW; n++) {
        int q0 = (ntb + n) * 8 + l4 * 2, q1 = q0 + 1;
        if (gv0 && q0 < QP1) out[((size_t)gb0 * QP1 + q0) * CNUM + gc0] = x[n][0];
        if (gv0 && q1 < QP1) out[((size_t)gb0 * QP1 + q1) * CNUM + gc0] = x[n][1];
        if (gv1 && q0 < QP1) out[((size_t)gb1 * QP1 + q0) * CNUM + gc1] = x[n][2];
        if (gv1 && q1 < QP1) out[((size_t)gb1 * QP1 + q1) * CNUM + gc1] = x[n][3];
    }
    #undef PBAR
}

extern "C" void kernel_launch(void* const* d_in, const int* in_sizes, int n_in,
                              void* d_out, int out_size)
{
    const float* series     = (const float*)d_in[0];
    const float* rand_error = (const float*)d_in[1];
    const float* W1 = (const float*)d_in[2];
    const float* b1 = (const float*)d_in[3];
    const float* W2 = (const float*)d_in[4];
    const float* b2 = (const float*)d_in[5];
    const float* W3 = (const float*)d_in[6];
    const float* b3 = (const float*)d_in[7];
    float* out = (float*)d_out;

    cudaFuncSetAttribute(arima_mma_kernel,
                         cudaFuncAttributeMaxDynamicSharedMemorySize, SMEM_TOTAL);
    arima_mma_kernel<<<GRID, NTHREADS, SMEM_TOTAL>>>(
        series, rand_error, W1, b1, W2, b2, W3, b3, out);
}